// round 2
// baseline (speedup 1.0000x reference)
#include <cuda_runtime.h>

// DenseMRConv: out[i] = concat(x[i], max_k(x[e[i,k]] - x[i])) @ W + b
// x: [N,64] f32, edge_index: [N,32] int (harness downcasts int64->int32),
// W: [128,64] f32, b: [64] f32, out: [N,64] f32

#define WARPS_PER_BLOCK 8
#define THREADS (WARPS_PER_BLOCK * 32)
#define D 64
#define KNBR 32
#define DIN 128  // 2*D

__global__ void __launch_bounds__(THREADS) mrconv_kernel(
    const float* __restrict__ x,
    const int* __restrict__ edge_index,
    const float* __restrict__ W,
    const float* __restrict__ b,
    float* __restrict__ out,
    int N)
{
    __shared__ float Ws[DIN * D];                 // 32 KB
    __shared__ float hs[WARPS_PER_BLOCK][DIN];    // 4 KB

    const int tid  = threadIdx.x;
    const int warp = tid >> 5;
    const int lane = tid & 31;

    // Stage W once per block (conflict-free, coalesced)
    for (int i = tid; i < DIN * D; i += THREADS) Ws[i] = W[i];
    __syncthreads();

    // Per-lane bias for the 2 output columns this lane owns
    const float b0 = b[2 * lane];
    const float b1 = b[2 * lane + 1];

    const float2* __restrict__ x2 = (const float2*)x;
    float2* __restrict__ out2 = (float2*)out;
    const float2* __restrict__ Ws2 = (const float2*)Ws;

    const int gwarp  = blockIdx.x * WARPS_PER_BLOCK + warp;
    const int nwarps = gridDim.x * WARPS_PER_BLOCK;

    for (int i = gwarp; i < N; i += nwarps) {
        // Load this node's features: lane owns dims {2*lane, 2*lane+1}
        const float2 xi = x2[i * (D / 2) + lane];

        // Coalesced load of all 32 neighbor indices (one per lane)
        const int myidx = edge_index[i * KNBR + lane];

        float2 dm = make_float2(-INFINITY, -INFINITY);
        #pragma unroll
        for (int k = 0; k < KNBR; k++) {
            const int j = __shfl_sync(0xffffffffu, myidx, k);
            const float2 xj = __ldg(&x2[j * (D / 2) + lane]);
            dm.x = fmaxf(dm.x, xj.x - xi.x);
            dm.y = fmaxf(dm.y, xj.y - xi.y);
        }

        // Stage h = [x_i, diff_max] into shared for the warp GEMM
        hs[warp][2 * lane]         = xi.x;
        hs[warp][2 * lane + 1]     = xi.y;
        hs[warp][D + 2 * lane]     = dm.x;
        hs[warp][D + 2 * lane + 1] = dm.y;
        __syncwarp();

        // out[i, 2*lane + {0,1}] = sum_d h[d] * W[d, 2*lane + {0,1}] + b
        float acc0 = b0, acc1 = b1;
        #pragma unroll 16
        for (int d = 0; d < DIN; d++) {
            const float hd = hs[warp][d];             // broadcast, conflict-free
            const float2 w = Ws2[d * (D / 2) + lane]; // 128B/phase, conflict-free
            acc0 = fmaf(hd, w.x, acc0);
            acc1 = fmaf(hd, w.y, acc1);
        }

        out2[i * (D / 2) + lane] = make_float2(acc0, acc1);
        __syncwarp();  // protect hs before next iteration overwrites it
    }
}

extern "C" void kernel_launch(void* const* d_in, const int* in_sizes, int n_in,
                              void* d_out, int out_size) {
    const float* x  = (const float*)d_in[0];
    const int*   ei = (const int*)d_in[1];
    const float* W  = (const float*)d_in[2];
    const float* b  = (const float*)d_in[3];
    float* out = (float*)d_out;

    const int N = in_sizes[0] / D;

    // ~6 blocks/SM by smem (36.75 KB/block of 228 KB), 148-152 SMs
    const int grid = 888;
    mrconv_kernel<<<grid, THREADS>>>(x, ei, W, b, out, N);
}

// round 3
// speedup vs baseline: 1.6003x; 1.6003x over previous
#include <cuda_runtime.h>

// DenseMRConv: out[i] = concat(x[i], max_k(x[e[i,k]] - x[i])) @ W + b
// x: [N,64] f32, edge_index: [N,32] int32, W: [128,64] f32, b: [64] f32, out: [N,64] f32
//
// Warp = M nodes. Lane owns output cols {2*lane, 2*lane+1} and input dims
// {2*lane, 2*lane+1}. Gather is 32 coalesced 256B row reads per node.
// Epilogue batches M nodes so the W shared-reads amortize 4x, and h is
// broadcast as float2 pairs (halves broadcast count).

#define WPB 8
#define THREADS (WPB * 32)
#define D 64
#define KNBR 32
#define DIN 128
#define MB 4   // nodes per warp batch

__global__ void __launch_bounds__(THREADS) mrconv_kernel(
    const float* __restrict__ x,
    const int* __restrict__ edge_index,
    const float* __restrict__ W,
    const float* __restrict__ b,
    float* __restrict__ out,
    int N)
{
    __shared__ float Ws[DIN * D];            // 32 KB
    __shared__ float2 hs[WPB][MB][D];        // 8*4*64*8 = 16 KB

    const int tid  = threadIdx.x;
    const int warp = tid >> 5;
    const int lane = tid & 31;

    for (int i = tid; i < DIN * D; i += THREADS) Ws[i] = W[i];
    __syncthreads();

    const float b0 = b[2 * lane];
    const float b1 = b[2 * lane + 1];

    const float2* __restrict__ x2  = (const float2*)x;
    float2* __restrict__ out2      = (float2*)out;
    const float2* __restrict__ Ws2 = (const float2*)Ws;

    const int gwarp  = blockIdx.x * WPB + warp;
    const int nwarps = gridDim.x * WPB;

    for (int i0 = gwarp * MB; i0 < N; i0 += nwarps * MB) {
        float2 xi[MB], dm[MB];
        int myidx[MB];

        #pragma unroll
        for (int m = 0; m < MB; m++) {
            const int i = min(i0 + m, N - 1);
            xi[m] = x2[i * (D / 2) + lane];
            myidx[m] = edge_index[i * KNBR + lane];
            dm[m] = make_float2(-INFINITY, -INFINITY);
        }

        #pragma unroll
        for (int m = 0; m < MB; m++) {
            #pragma unroll 16
            for (int k = 0; k < KNBR; k++) {
                const int j = __shfl_sync(0xffffffffu, myidx[m], k);
                const float2 xj = __ldg(&x2[j * (D / 2) + lane]);
                dm[m].x = fmaxf(dm[m].x, xj.x - xi[m].x);
                dm[m].y = fmaxf(dm[m].y, xj.y - xi[m].y);
            }
        }

        // Stage h = [x_i (64), diff_max (64)] as 64 float2 per node
        #pragma unroll
        for (int m = 0; m < MB; m++) {
            hs[warp][m][lane]      = xi[m];
            hs[warp][m][32 + lane] = dm[m];
        }
        __syncwarp();

        float2 acc[MB];
        #pragma unroll
        for (int m = 0; m < MB; m++) acc[m] = make_float2(b0, b1);

        #pragma unroll 8
        for (int d2 = 0; d2 < D; d2++) {           // d = 2*d2, 2*d2+1
            const float2 w0 = Ws2[(2 * d2)     * (D / 2) + lane];
            const float2 w1 = Ws2[(2 * d2 + 1) * (D / 2) + lane];
            #pragma unroll
            for (int m = 0; m < MB; m++) {
                const float2 h = hs[warp][m][d2];  // 8B broadcast, 1 wavefront
                acc[m].x = fmaf(h.x, w0.x, acc[m].x);
                acc[m].y = fmaf(h.x, w0.y, acc[m].y);
                acc[m].x = fmaf(h.y, w1.x, acc[m].x);
                acc[m].y = fmaf(h.y, w1.y, acc[m].y);
            }
        }

        #pragma unroll
        for (int m = 0; m < MB; m++)
            if (i0 + m < N) out2[(i0 + m) * (D / 2) + lane] = acc[m];
        __syncwarp();  // protect hs before next batch overwrites it
    }
}

extern "C" void kernel_launch(void* const* d_in, const int* in_sizes, int n_in,
                              void* d_out, int out_size) {
    const float* x  = (const float*)d_in[0];
    const int*   ei = (const int*)d_in[1];
    const float* W  = (const float*)d_in[2];
    const float* b  = (const float*)d_in[3];
    float* out = (float*)d_out;

    const int N = in_sizes[0] / D;

    // 48.25 KB smem/block -> 4 blocks/SM, 152 SMs on GB300
    const int grid = 608;
    mrconv_kernel<<<grid, THREADS>>>(x, ei, W, b, out, N);
}

// round 4
// speedup vs baseline: 1.7078x; 1.0671x over previous
#include <cuda_runtime.h>

// DenseMRConv: out[i] = concat(x[i], max_k(x[e[i,k]] - x[i])) @ W + b
// x: [N,64] f32, edge_index: [N,32] int32, W: [128,64] f32, b: [64] f32, out: [N,64] f32
//
// Warp batches MB=8 nodes. Lane owns output cols {2l,2l+1} and input dims {2l,2l+1}.
// W is pre-permuted in smem so per 4-dim group each lane does 2 conflict-free
// LDS.128; h is broadcast as float4 (1 wavefront per 4 dims per node).

#define WPB 8
#define THREADS (WPB * 32)
#define D 64
#define KNBR 32
#define DIN 128
#define MB 8

// dynamic smem: Wp[32][2][32] float4 (32KB) then hs4[WPB*MB][32] float4 (32KB)
#define WP_F4   2048
#define HS_F4   (WPB * MB * 32)
#define SMEM_BYTES ((WP_F4 + HS_F4) * 16)

__global__ void __launch_bounds__(THREADS, 3) mrconv_kernel(
    const float* __restrict__ x,
    const int* __restrict__ edge_index,
    const float* __restrict__ W,
    const float* __restrict__ b,
    float* __restrict__ out,
    int N)
{
    extern __shared__ float4 sm[];
    float4* __restrict__ Wp  = sm;            // [d4][half][lane]
    float4* __restrict__ hs4 = sm + WP_F4;    // [(warp*MB+m)][d4]

    const int tid  = threadIdx.x;
    const int warp = tid >> 5;
    const int lane = tid & 31;

    // Stage permuted W: Wp[d4][h][l] = {W[db][2l],W[db][2l+1],W[db+1][2l],W[db+1][2l+1]},
    // db = 4*d4 + 2*h. One-time, coalesced float2 global reads.
    {
        const float2* W2 = (const float2*)W;   // W2[d*32 + c2] = {W[d][2c2],W[d][2c2+1]}
        for (int e = tid; e < WP_F4; e += THREADS) {
            const int l  = e & 31;
            const int h  = (e >> 5) & 1;
            const int d4 = e >> 6;
            const int db = 4 * d4 + 2 * h;
            const float2 a0 = W2[db * 32 + l];
            const float2 a1 = W2[(db + 1) * 32 + l];
            Wp[e] = make_float4(a0.x, a0.y, a1.x, a1.y);
        }
    }
    __syncthreads();

    const float b0 = b[2 * lane];
    const float b1 = b[2 * lane + 1];

    const float2* __restrict__ x2 = (const float2*)x;
    float2* __restrict__ out2     = (float2*)out;
    float2* __restrict__ hs2      = (float2*)hs4;   // 64 float2 slots per (warp,m)

    const int gwarp  = blockIdx.x * WPB + warp;
    const int nwarps = gridDim.x * WPB;

    for (int i0 = gwarp * MB; i0 < N; i0 += nwarps * MB) {
        float2 xi[MB], dm[MB];
        int myidx[MB];

        #pragma unroll
        for (int m = 0; m < MB; m++) {
            const int i = min(i0 + m, N - 1);
            xi[m]    = x2[i * (D / 2) + lane];
            myidx[m] = edge_index[i * KNBR + lane];
            dm[m]    = make_float2(-INFINITY, -INFINITY);
        }

        #pragma unroll
        for (int m = 0; m < MB; m++) {
            #pragma unroll 16
            for (int k = 0; k < KNBR; k++) {
                const int j = __shfl_sync(0xffffffffu, myidx[m], k);
                const float2 xj = __ldg(&x2[j * (D / 2) + lane]);
                dm[m].x = fmaxf(dm[m].x, xj.x - xi[m].x);
                dm[m].y = fmaxf(dm[m].y, xj.y - xi[m].y);
            }
        }

        // Stage h = [x (slots 0..31), diff_max (slots 32..63)] per node
        #pragma unroll
        for (int m = 0; m < MB; m++) {
            const int base = (warp * MB + m) * 64;
            hs2[base + lane]      = xi[m];
            hs2[base + 32 + lane] = dm[m];
        }
        __syncwarp();

        float2 acc[MB];
        #pragma unroll
        for (int m = 0; m < MB; m++) acc[m] = make_float2(b0, b1);

        #pragma unroll 4
        for (int d4 = 0; d4 < 32; d4++) {          // dims 4*d4 .. 4*d4+3
            const float4 wA = Wp[d4 * 64 + lane];
            const float4 wB = Wp[d4 * 64 + 32 + lane];
            #pragma unroll
            for (int m = 0; m < MB; m++) {
                const float4 h = hs4[(warp * MB + m) * 32 + d4]; // uniform: 1 wavefront
                acc[m].x = fmaf(h.x, wA.x, acc[m].x);
                acc[m].y = fmaf(h.x, wA.y, acc[m].y);
                acc[m].x = fmaf(h.y, wA.z, acc[m].x);
                acc[m].y = fmaf(h.y, wA.w, acc[m].y);
                acc[m].x = fmaf(h.z, wB.x, acc[m].x);
                acc[m].y = fmaf(h.z, wB.y, acc[m].y);
                acc[m].x = fmaf(h.w, wB.z, acc[m].x);
                acc[m].y = fmaf(h.w, wB.w, acc[m].y);
            }
        }

        #pragma unroll
        for (int m = 0; m < MB; m++)
            if (i0 + m < N) out2[(i0 + m) * (D / 2) + lane] = acc[m];
        __syncwarp();  // protect hs before next batch overwrites it
    }
}

extern "C" void kernel_launch(void* const* d_in, const int* in_sizes, int n_in,
                              void* d_out, int out_size) {
    const float* x  = (const float*)d_in[0];
    const int*   ei = (const int*)d_in[1];
    const float* W  = (const float*)d_in[2];
    const float* b  = (const float*)d_in[3];
    float* out = (float*)d_out;

    const int N = in_sizes[0] / D;

    static int smem_set = 0;
    if (!smem_set) {
        cudaFuncSetAttribute(mrconv_kernel,
                             cudaFuncAttributeMaxDynamicSharedMemorySize, SMEM_BYTES);
        smem_set = 1;
    }

    // 64 KB smem/block -> 3 blocks/SM, 152 SMs
    const int grid = 456;
    mrconv_kernel<<<grid, THREADS, SMEM_BYTES>>>(x, ei, W, b, out, N);
}